// round 8
// baseline (speedup 1.0000x reference)
#include <cuda_runtime.h>
#include <cuda_bf16.h>
#include <cstdint>

typedef unsigned long long u64;

// Problem dims
#define TT 2048
#define BB 16
#define II 512
#define HH 512
#define BH (BB*HH)   // 8192

#define CLUSTER 8    // CTAs per cluster = 1 batch per cluster, 64 cols per CTA

static __device__ __forceinline__ uint32_t smem_u32(const void* p) {
    uint32_t a;
    asm("{ .reg .u64 t; cvta.to.shared.u64 t, %1; cvt.u32.u64 %0, t; }"
        : "=r"(a) : "l"(p));
    return a;
}

// ---------------------------------------------------------------------------
// Kernel 1: x_proj GEMM (unchanged; ~0.4ms, fma-bound)
// ---------------------------------------------------------------------------
__global__ __launch_bounds__(256)
void xproj_kernel(const float* __restrict__ A,      // inputs [M][512]
                  const float* __restrict__ W,      // weight [512][1024]
                  const float* __restrict__ bias,   // [512]
                  float* __restrict__ out)          // [M][512]
{
    __shared__ float As[32][132];
    __shared__ float Bs[32][68];

    const int tid = threadIdx.x;
    const int bm = blockIdx.x * 128;
    const int bn = blockIdx.y * 64;

    const int tx = tid & 15;
    const int ty = tid >> 4;

    float acc[8][4];
#pragma unroll
    for (int r = 0; r < 8; r++)
#pragma unroll
        for (int c = 0; c < 4; c++) acc[r][c] = 0.f;

#pragma unroll 1
    for (int kt = 0; kt < 16; kt++) {
        const int k0 = kt * 32;
#pragma unroll
        for (int j = 0; j < 4; j++) {
            int idx = tid + j * 256;
            int row = idx >> 3;
            int q   = idx & 7;
            float4 v = *reinterpret_cast<const float4*>(&A[(size_t)(bm + row) * 512 + k0 + q * 4]);
            As[q * 4 + 0][row] = v.x;
            As[q * 4 + 1][row] = v.y;
            As[q * 4 + 2][row] = v.z;
            As[q * 4 + 3][row] = v.w;
        }
#pragma unroll
        for (int j = 0; j < 2; j++) {
            int idx = tid + j * 256;
            int row = idx >> 3;
            int q   = idx & 7;
            float4 v = *reinterpret_cast<const float4*>(&W[(size_t)(bn + row) * 1024 + 512 + k0 + q * 4]);
            Bs[q * 4 + 0][row] = v.x;
            Bs[q * 4 + 1][row] = v.y;
            Bs[q * 4 + 2][row] = v.z;
            Bs[q * 4 + 3][row] = v.w;
        }
        __syncthreads();

#pragma unroll
        for (int k = 0; k < 32; k++) {
            float4 a0 = *reinterpret_cast<const float4*>(&As[k][ty * 8]);
            float4 a1 = *reinterpret_cast<const float4*>(&As[k][ty * 8 + 4]);
            float4 b  = *reinterpret_cast<const float4*>(&Bs[k][tx * 4]);
            float av[8] = {a0.x, a0.y, a0.z, a0.w, a1.x, a1.y, a1.z, a1.w};
            float bv[4] = {b.x, b.y, b.z, b.w};
#pragma unroll
            for (int r = 0; r < 8; r++)
#pragma unroll
                for (int c = 0; c < 4; c++)
                    acc[r][c] = fmaf(av[r], bv[c], acc[r][c]);
        }
        __syncthreads();
    }

#pragma unroll
    for (int r = 0; r < 8; r++) {
        size_t row = (size_t)(bm + ty * 8 + r) * 512 + bn + tx * 4;
#pragma unroll
        for (int c = 0; c < 4; c++)
            out[row + c] = acc[r][c] + bias[bn + tx * 4 + c];
    }
}

// ---------------------------------------------------------------------------
// Kernel 2: cluster scan. Publish via 8x cp.async.bulk (256B) instead of 512
// scalar st.async -> 8 tx-updates per destination barrier per step.
// 16 clusters x 8 CTAs; cluster = batch; rank owns 64 cols; thread
// (col=tid&63, ks=tid>>6); W_hh slice in registers (f32x2).
// ---------------------------------------------------------------------------
__global__ void __cluster_dims__(CLUSTER, 1, 1) __launch_bounds__(512, 1)
scan_kernel(const float* __restrict__ weight,  // [512][1024], w_hh = cols [0,512)
            const float* __restrict__ state,   // [16][512]
            float* __restrict__ out)           // [T][16][512] + last [16][512]
{
    __shared__ float hsh[2][512];                    // double-buffered h
    __shared__ float red[2][8][65];                  // double-buffered partials
    __shared__ __align__(16) float hstage[64];       // publish staging
    __shared__ __align__(8) u64 mbar[2];             // full[buf] barriers

    const int tid  = threadIdx.x;
    const int col  = tid & 63;
    const int ks   = tid >> 6;                 // k in [ks*64, ks*64+64)
    const int rank = blockIdx.x & (CLUSTER - 1);
    const int b    = blockIdx.x / CLUSTER;     // batch
    const int c0   = rank * 64;
    const int gcol = c0 + col;

    // ---- W_hh slice into registers (f32x2-packed over k) ----
    u64 wreg[32];
    {
        const u64* wp = reinterpret_cast<const u64*>(
            weight + (size_t)gcol * 1024 + ks * 64);
#pragma unroll
        for (int j = 0; j < 32; j += 2) {
            ulonglong2 v = *reinterpret_cast<const ulonglong2*>(wp + j);
            wreg[j]     = v.x;
            wreg[j + 1] = v.y;
        }
    }

    // ---- init: h_0, barriers, cluster-wide visibility ----
    hsh[0][tid] = state[(size_t)b * 512 + tid];
    const uint32_t bar0 = smem_u32(&mbar[0]);
    const uint32_t bar1 = smem_u32(&mbar[1]);
    if (tid == 0) {
        asm volatile("mbarrier.init.shared.b64 [%0], 1;" :: "r"(bar0) : "memory");
        asm volatile("mbarrier.init.shared.b64 [%0], 1;" :: "r"(bar1) : "memory");
    }
    __syncthreads();
    asm volatile("barrier.cluster.arrive.aligned;" ::: "memory");
    asm volatile("barrier.cluster.wait.aligned;" ::: "memory");

    // ---- prefetch x_proj for t=0 ----
    float xp = 0.f;
    if (tid < 64)
        xp = __ldcg(out + (size_t)b * 512 + c0 + tid);

    // local addresses for bulk publish (dst = own columns' slot in each peer)
    const uint32_t ldst_h0 = smem_u32(&hsh[0][c0]);
    const uint32_t ldst_h1 = smem_u32(&hsh[1][c0]);
    const uint32_t lsrc    = smem_u32(&hstage[0]);

#pragma unroll 1
    for (int t = 0; t < TT; t++) {
        const int rb = t & 1;
        const uint32_t barw = rb ? bar1 : bar0;

        // ---- 1. wait for h_{t-1} (2048 tx bytes = 8 chunks x 256B) ----
        if (t > 0) {
            if (tid == 0)
                asm volatile("mbarrier.arrive.expect_tx.shared.b64 _, [%0], 2048;"
                             :: "r"(barw) : "memory");
            const uint32_t parity = ((unsigned)(t - 1) >> 1) & 1u;
            uint32_t done;
            asm volatile(
                "{\n\t.reg .pred p;\n\t"
                "mbarrier.try_wait.parity.acquire.cta.shared::cta.b64 p, [%1], %2;\n\t"
                "selp.b32 %0, 1, 0, p;\n\t}"
                : "=r"(done) : "r"(barw), "r"(parity) : "memory");
            while (!done) {
                asm volatile(
                    "{\n\t.reg .pred p;\n\t"
                    "mbarrier.try_wait.parity.acquire.cta.shared::cta.b64 p, [%1], %2, 0x989680;\n\t"
                    "selp.b32 %0, 1, 0, p;\n\t}"
                    : "=r"(done) : "r"(barw), "r"(parity) : "memory");
            }
        }

        // ---- 2. compute: packed f32x2 dot over this thread's 64 k's ----
        u64 accp = 0ull;
        const u64* hp = reinterpret_cast<const u64*>(&hsh[rb][ks * 64]);
#pragma unroll
        for (int j = 0; j < 32; j += 2) {
            ulonglong2 h2 = *reinterpret_cast<const ulonglong2*>(hp + j);
            asm("fma.rn.f32x2 %0, %1, %2, %0;"
                : "+l"(accp) : "l"(wreg[j]),     "l"(h2.x));
            asm("fma.rn.f32x2 %0, %1, %2, %0;"
                : "+l"(accp) : "l"(wreg[j + 1]), "l"(h2.y));
        }
        {
            uint32_t lo, hi;
            asm("mov.b64 {%0, %1}, %2;" : "=r"(lo), "=r"(hi) : "l"(accp));
            red[rb][ks][col] = __uint_as_float(lo) + __uint_as_float(hi);
        }

        // ---- 3. split barrier: producers arrive and loop; finalizers sync ----
        if (tid >= 64) {
            asm volatile("bar.arrive 3, 512;" ::: "memory");
            continue;   // straight to next step's mbarrier wait
        }
        asm volatile("bar.sync 3, 512;" ::: "memory");

        // ---- 4. finalize (warps 0-1): reduce, bulk publish, store out ----
        {
            float s = 0.f;
#pragma unroll
            for (int r = 0; r < 8; r++) s += red[rb][r][tid];
            const float hn = s + xp;

            if (t + 1 < TT) {
                // make sure last step's outbound bulk reads of hstage are done
                if (tid == 0)
                    asm volatile("cp.async.bulk.wait_group.read 0;" ::: "memory");
                asm volatile("bar.sync 1, 64;" ::: "memory");
                hstage[tid] = hn;
                asm volatile("bar.sync 1, 64;" ::: "memory");
                if (tid == 0) {
                    asm volatile("fence.proxy.async.shared::cta;" ::: "memory");
                    const uint32_t ldst = rb ? ldst_h0 : ldst_h1;  // buffer rb^1
                    const uint32_t lbar = rb ? bar0 : bar1;
#pragma unroll
                    for (int r = 0; r < CLUSTER; r++) {
                        uint32_t raddr, rbar;
                        asm volatile("mapa.shared::cluster.u32 %0, %1, %2;"
                                     : "=r"(raddr) : "r"(ldst), "r"(r));
                        asm volatile("mapa.shared::cluster.u32 %0, %1, %2;"
                                     : "=r"(rbar) : "r"(lbar), "r"(r));
                        asm volatile(
                            "cp.async.bulk.shared::cluster.shared::cta.mbarrier::complete_tx::bytes"
                            " [%0], [%1], %2, [%3];"
                            :: "r"(raddr), "r"(lsrc), "r"(256u), "r"(rbar) : "memory");
                    }
                    asm volatile("cp.async.bulk.commit_group;" ::: "memory");
                }
            }

            const size_t off = (size_t)t * BH + (size_t)b * HH + c0 + tid;
            __stcg(out + off, hn);
            if (t == TT - 1)
                __stcg(out + (size_t)TT * BH + (size_t)b * HH + c0 + tid, hn);
            if (t + 1 < TT)
                xp = __ldcg(out + (size_t)(t + 1) * BH + (size_t)b * HH + c0 + tid);
        }
    }

    // ---- drain: no CTA exits while peers might still target its SMEM ----
    asm volatile("barrier.cluster.arrive.aligned;" ::: "memory");
    asm volatile("barrier.cluster.wait.aligned;" ::: "memory");
}

// ---------------------------------------------------------------------------
// Launch
// ---------------------------------------------------------------------------
extern "C" void kernel_launch(void* const* d_in, const int* in_sizes, int n_in,
                              void* d_out, int out_size) {
    const float* inputs = (const float*)d_in[0];  // [T][B][I]
    const float* state  = (const float*)d_in[1];  // [B][H]
    const float* weight = (const float*)d_in[2];  // [H][I+H]
    const float* bias   = (const float*)d_in[3];  // [H]
    float* out = (float*)d_out;                   // [T][B][H] outputs, then [B][H] last

    dim3 g1(256, 8);
    xproj_kernel<<<g1, 256>>>(inputs, weight, bias, out);

    scan_kernel<<<BB * CLUSTER, 512>>>(weight, state, out);

    (void)in_sizes; (void)n_in; (void)out_size;
}

// round 9
// speedup vs baseline: 1.2538x; 1.2538x over previous
#include <cuda_runtime.h>
#include <cuda_bf16.h>
#include <cstdint>

typedef unsigned long long u64;

// Problem dims
#define TT 2048
#define BB 16
#define II 512
#define HH 512
#define BH (BB*HH)   // 8192

#define CLUSTER 8    // CTAs per cluster = 1 batch per cluster, 64 cols per CTA

static __device__ __forceinline__ uint32_t smem_u32(const void* p) {
    uint32_t a;
    asm("{ .reg .u64 t; cvta.to.shared.u64 t, %1; cvt.u32.u64 %0, t; }"
        : "=r"(a) : "l"(p));
    return a;
}

// ---------------------------------------------------------------------------
// Kernel 1: x_proj GEMM (unchanged; ~0.4ms, fma-bound)
// ---------------------------------------------------------------------------
__global__ __launch_bounds__(256)
void xproj_kernel(const float* __restrict__ A,      // inputs [M][512]
                  const float* __restrict__ W,      // weight [512][1024]
                  const float* __restrict__ bias,   // [512]
                  float* __restrict__ out)          // [M][512]
{
    __shared__ float As[32][132];
    __shared__ float Bs[32][68];

    const int tid = threadIdx.x;
    const int bm = blockIdx.x * 128;
    const int bn = blockIdx.y * 64;

    const int tx = tid & 15;
    const int ty = tid >> 4;

    float acc[8][4];
#pragma unroll
    for (int r = 0; r < 8; r++)
#pragma unroll
        for (int c = 0; c < 4; c++) acc[r][c] = 0.f;

#pragma unroll 1
    for (int kt = 0; kt < 16; kt++) {
        const int k0 = kt * 32;
#pragma unroll
        for (int j = 0; j < 4; j++) {
            int idx = tid + j * 256;
            int row = idx >> 3;
            int q   = idx & 7;
            float4 v = *reinterpret_cast<const float4*>(&A[(size_t)(bm + row) * 512 + k0 + q * 4]);
            As[q * 4 + 0][row] = v.x;
            As[q * 4 + 1][row] = v.y;
            As[q * 4 + 2][row] = v.z;
            As[q * 4 + 3][row] = v.w;
        }
#pragma unroll
        for (int j = 0; j < 2; j++) {
            int idx = tid + j * 256;
            int row = idx >> 3;
            int q   = idx & 7;
            float4 v = *reinterpret_cast<const float4*>(&W[(size_t)(bn + row) * 1024 + 512 + k0 + q * 4]);
            Bs[q * 4 + 0][row] = v.x;
            Bs[q * 4 + 1][row] = v.y;
            Bs[q * 4 + 2][row] = v.z;
            Bs[q * 4 + 3][row] = v.w;
        }
        __syncthreads();

#pragma unroll
        for (int k = 0; k < 32; k++) {
            float4 a0 = *reinterpret_cast<const float4*>(&As[k][ty * 8]);
            float4 a1 = *reinterpret_cast<const float4*>(&As[k][ty * 8 + 4]);
            float4 b  = *reinterpret_cast<const float4*>(&Bs[k][tx * 4]);
            float av[8] = {a0.x, a0.y, a0.z, a0.w, a1.x, a1.y, a1.z, a1.w};
            float bv[4] = {b.x, b.y, b.z, b.w};
#pragma unroll
            for (int r = 0; r < 8; r++)
#pragma unroll
                for (int c = 0; c < 4; c++)
                    acc[r][c] = fmaf(av[r], bv[c], acc[r][c]);
        }
        __syncthreads();
    }

#pragma unroll
    for (int r = 0; r < 8; r++) {
        size_t row = (size_t)(bm + ty * 8 + r) * 512 + bn + tx * 4;
#pragma unroll
        for (int c = 0; c < 4; c++)
            out[row + c] = acc[r][c] + bias[bn + tx * 4 + c];
    }
}

// ---------------------------------------------------------------------------
// Kernel 2: cluster scan (= the 2958us R5 kernel, with ONE change:
// publish is 128x st.async.v4 (16B) instead of 512x scalar st.async (4B),
// cutting destination-mbarrier tx-updates 4x).
// 16 clusters x 8 CTAs; cluster = batch; rank owns 64 cols; thread
// (col=tid&63, ks=tid>>6); W_hh slice in registers (f32x2).
// ---------------------------------------------------------------------------
__global__ void __cluster_dims__(CLUSTER, 1, 1) __launch_bounds__(512, 1)
scan_kernel(const float* __restrict__ weight,  // [512][1024], w_hh = cols [0,512)
            const float* __restrict__ state,   // [16][512]
            float* __restrict__ out)           // [T][16][512] + last [16][512]
{
    __shared__ __align__(16) float hsh[2][512];     // double-buffered h
    __shared__ float red[8][65];                    // k-split partials
    __shared__ __align__(16) float hstage[2][64];   // publish staging (dbl-buf)
    __shared__ __align__(8) u64 mbar[2];            // full[buf] barriers

    const int tid  = threadIdx.x;
    const int col  = tid & 63;
    const int ks   = tid >> 6;                 // k in [ks*64, ks*64+64)
    const int rank = blockIdx.x & (CLUSTER - 1);
    const int b    = blockIdx.x / CLUSTER;     // batch
    const int c0   = rank * 64;
    const int gcol = c0 + col;

    // ---- W_hh slice into registers (f32x2-packed over k) ----
    u64 wreg[32];
    {
        const u64* wp = reinterpret_cast<const u64*>(
            weight + (size_t)gcol * 1024 + ks * 64);
#pragma unroll
        for (int j = 0; j < 32; j += 2) {
            ulonglong2 v = *reinterpret_cast<const ulonglong2*>(wp + j);
            wreg[j]     = v.x;
            wreg[j + 1] = v.y;
        }
    }

    // ---- init: h_0, barriers, cluster-wide visibility ----
    hsh[0][tid] = state[(size_t)b * 512 + tid];
    const uint32_t bar0 = smem_u32(&mbar[0]);
    const uint32_t bar1 = smem_u32(&mbar[1]);
    if (tid == 0) {
        asm volatile("mbarrier.init.shared.b64 [%0], 1;" :: "r"(bar0) : "memory");
        asm volatile("mbarrier.init.shared.b64 [%0], 1;" :: "r"(bar1) : "memory");
    }
    __syncthreads();
    asm volatile("barrier.cluster.arrive.aligned;" ::: "memory");
    asm volatile("barrier.cluster.wait.aligned;" ::: "memory");

    // ---- prefetch x_proj for t=0 ----
    float xp = 0.f;
    if (tid < 64)
        xp = __ldcg(out + (size_t)b * 512 + c0 + tid);

    // publish geometry (finalize threads tid<64): thread i -> dest d, 32B slice
    const int pd = tid >> 3;        // destination rank 0..7
    const int pq = tid & 7;         // 32B slice index within the 256B message
    // local byte address of the slice inside hsh[buf]: &hsh[buf][c0 + 8*pq]
    const uint32_t ldst_h0 = smem_u32(&hsh[0][c0]) + pq * 32;
    const uint32_t ldst_h1 = smem_u32(&hsh[1][c0]) + pq * 32;

#pragma unroll 1
    for (int t = 0; t < TT; t++) {
        const int rb = t & 1;
        const uint32_t barw = rb ? bar1 : bar0;

        // ---- 1. wait for h_{t-1} (2048 tx bytes = 128 x 16B) ----
        if (t > 0) {
            if (tid == 0)
                asm volatile("mbarrier.arrive.expect_tx.shared.b64 _, [%0], 2048;"
                             :: "r"(barw) : "memory");
            const uint32_t parity = ((unsigned)(t - 1) >> 1) & 1u;
            uint32_t done;
            asm volatile(
                "{\n\t.reg .pred p;\n\t"
                "mbarrier.try_wait.parity.acquire.cta.shared::cta.b64 p, [%1], %2;\n\t"
                "selp.b32 %0, 1, 0, p;\n\t}"
                : "=r"(done) : "r"(barw), "r"(parity) : "memory");
            while (!done) {
                asm volatile(
                    "{\n\t.reg .pred p;\n\t"
                    "mbarrier.try_wait.parity.acquire.cta.shared::cta.b64 p, [%1], %2, 0x989680;\n\t"
                    "selp.b32 %0, 1, 0, p;\n\t}"
                    : "=r"(done) : "r"(barw), "r"(parity) : "memory");
            }
        }

        // ---- 2. compute: packed f32x2 dot over this thread's 64 k's ----
        u64 accp = 0ull;
        const u64* hp = reinterpret_cast<const u64*>(&hsh[rb][ks * 64]);
#pragma unroll
        for (int j = 0; j < 32; j += 2) {
            ulonglong2 h2 = *reinterpret_cast<const ulonglong2*>(hp + j);
            asm("fma.rn.f32x2 %0, %1, %2, %0;"
                : "+l"(accp) : "l"(wreg[j]),     "l"(h2.x));
            asm("fma.rn.f32x2 %0, %1, %2, %0;"
                : "+l"(accp) : "l"(wreg[j + 1]), "l"(h2.y));
        }
        {
            uint32_t lo, hi;
            asm("mov.b64 {%0, %1}, %2;" : "=r"(lo), "=r"(hi) : "l"(accp));
            red[ks][col] = __uint_as_float(lo) + __uint_as_float(hi);
        }
        __syncthreads();

        // ---- 3. finalize (tid<64): reduce, stage, v4 publish, store out ----
        if (tid < 64) {
            float s = 0.f;
#pragma unroll
            for (int r = 0; r < 8; r++) s += red[r][tid];
            const float hn = s + xp;

            if (t + 1 < TT) {
                hstage[rb][tid] = hn;
                asm volatile("bar.sync 1, 64;" ::: "memory");
                // read my 32B slice and push it to my destination CTA
                const float4* src = reinterpret_cast<const float4*>(&hstage[rb][pq * 8]);
                float4 v0 = src[0];
                float4 v1 = src[1];
                const uint32_t ldst = rb ? ldst_h0 : ldst_h1;   // buffer rb^1
                const uint32_t lbar = rb ? bar0 : bar1;
                uint32_t raddr, rbar;
                asm volatile("mapa.shared::cluster.u32 %0, %1, %2;"
                             : "=r"(raddr) : "r"(ldst), "r"(pd));
                asm volatile("mapa.shared::cluster.u32 %0, %1, %2;"
                             : "=r"(rbar) : "r"(lbar), "r"(pd));
                asm volatile(
                    "st.async.weak.shared::cluster.mbarrier::complete_tx::bytes.v4.b32"
                    " [%0], {%1,%2,%3,%4}, [%5];"
                    :: "r"(raddr),
                       "r"(__float_as_uint(v0.x)), "r"(__float_as_uint(v0.y)),
                       "r"(__float_as_uint(v0.z)), "r"(__float_as_uint(v0.w)),
                       "r"(rbar) : "memory");
                asm volatile(
                    "st.async.weak.shared::cluster.mbarrier::complete_tx::bytes.v4.b32"
                    " [%0], {%1,%2,%3,%4}, [%5];"
                    :: "r"(raddr + 16),
                       "r"(__float_as_uint(v1.x)), "r"(__float_as_uint(v1.y)),
                       "r"(__float_as_uint(v1.z)), "r"(__float_as_uint(v1.w)),
                       "r"(rbar) : "memory");
            }

            const size_t off = (size_t)t * BH + (size_t)b * HH + c0 + tid;
            __stcg(out + off, hn);
            if (t == TT - 1)
                __stcg(out + (size_t)TT * BH + (size_t)b * HH + c0 + tid, hn);
            if (t + 1 < TT)
                xp = __ldcg(out + (size_t)(t + 1) * BH + (size_t)b * HH + c0 + tid);
        }
    }

    // ---- drain: no CTA exits while peers might still target its SMEM ----
    asm volatile("barrier.cluster.arrive.aligned;" ::: "memory");
    asm volatile("barrier.cluster.wait.aligned;" ::: "memory");
}

// ---------------------------------------------------------------------------
// Launch
// ---------------------------------------------------------------------------
extern "C" void kernel_launch(void* const* d_in, const int* in_sizes, int n_in,
                              void* d_out, int out_size) {
    const float* inputs = (const float*)d_in[0];  // [T][B][I]
    const float* state  = (const float*)d_in[1];  // [B][H]
    const float* weight = (const float*)d_in[2];  // [H][I+H]
    const float* bias   = (const float*)d_in[3];  // [H]
    float* out = (float*)d_out;                   // [T][B][H] outputs, then [B][H] last

    dim3 g1(256, 8);
    xproj_kernel<<<g1, 256>>>(inputs, weight, bias, out);

    scan_kernel<<<BB * CLUSTER, 512>>>(weight, state, out);

    (void)in_sizes; (void)n_in; (void)out_size;
}

// round 10
// speedup vs baseline: 2.2016x; 1.7559x over previous
#include <cuda_runtime.h>
#include <cuda_bf16.h>
#include <cstdint>

typedef unsigned long long u64;

// Problem dims
#define TT 2048
#define BB 16
#define II 512
#define HH 512
#define BH (BB*HH)   // 8192
#define RR (TT/2)    // 1024 scan rounds

#define CLUSTER 8    // CTAs per cluster = 1 batch per cluster, 64 cols per CTA

// Scratch: W^2, row-major [512][512]. Static __device__ allocation (legal).
__device__ float g_W2[HH * HH];

static __device__ __forceinline__ uint32_t smem_u32(const void* p) {
    uint32_t a;
    asm("{ .reg .u64 t; cvta.to.shared.u64 t, %1; cvt.u32.u64 %0, t; }"
        : "=r"(a) : "l"(p));
    return a;
}

// ---------------------------------------------------------------------------
// Kernel 1: x_proj[t,b,h] = sum_i inputs[t,b,i] * w_xh[h][i] + bias[h]
// (proven; ~0.40 ms, fma-bound)
// ---------------------------------------------------------------------------
__global__ __launch_bounds__(256)
void xproj_kernel(const float* __restrict__ A,      // inputs [M][512]
                  const float* __restrict__ W,      // weight [512][1024]
                  const float* __restrict__ bias,   // [512]
                  float* __restrict__ out)          // [M][512]
{
    __shared__ float As[32][132];
    __shared__ float Bs[32][68];

    const int tid = threadIdx.x;
    const int bm = blockIdx.x * 128;
    const int bn = blockIdx.y * 64;

    const int tx = tid & 15;
    const int ty = tid >> 4;

    float acc[8][4];
#pragma unroll
    for (int r = 0; r < 8; r++)
#pragma unroll
        for (int c = 0; c < 4; c++) acc[r][c] = 0.f;

#pragma unroll 1
    for (int kt = 0; kt < 16; kt++) {
        const int k0 = kt * 32;
#pragma unroll
        for (int j = 0; j < 4; j++) {
            int idx = tid + j * 256;
            int row = idx >> 3;
            int q   = idx & 7;
            float4 v = *reinterpret_cast<const float4*>(&A[(size_t)(bm + row) * 512 + k0 + q * 4]);
            As[q * 4 + 0][row] = v.x;
            As[q * 4 + 1][row] = v.y;
            As[q * 4 + 2][row] = v.z;
            As[q * 4 + 3][row] = v.w;
        }
#pragma unroll
        for (int j = 0; j < 2; j++) {
            int idx = tid + j * 256;
            int row = idx >> 3;
            int q   = idx & 7;
            float4 v = *reinterpret_cast<const float4*>(&W[(size_t)(bn + row) * 1024 + 512 + k0 + q * 4]);
            Bs[q * 4 + 0][row] = v.x;
            Bs[q * 4 + 1][row] = v.y;
            Bs[q * 4 + 2][row] = v.z;
            Bs[q * 4 + 3][row] = v.w;
        }
        __syncthreads();

#pragma unroll
        for (int k = 0; k < 32; k++) {
            float4 a0 = *reinterpret_cast<const float4*>(&As[k][ty * 8]);
            float4 a1 = *reinterpret_cast<const float4*>(&As[k][ty * 8 + 4]);
            float4 b  = *reinterpret_cast<const float4*>(&Bs[k][tx * 4]);
            float av[8] = {a0.x, a0.y, a0.z, a0.w, a1.x, a1.y, a1.z, a1.w};
            float bv[4] = {b.x, b.y, b.z, b.w};
#pragma unroll
            for (int r = 0; r < 8; r++)
#pragma unroll
                for (int c = 0; c < 4; c++)
                    acc[r][c] = fmaf(av[r], bv[c], acc[r][c]);
        }
        __syncthreads();
    }

#pragma unroll
    for (int r = 0; r < 8; r++) {
        size_t row = (size_t)(bm + ty * 8 + r) * 512 + bn + tx * 4;
#pragma unroll
        for (int c = 0; c < 4; c++)
            out[row + c] = acc[r][c] + bias[bn + tx * 4 + c];
    }
}

// ---------------------------------------------------------------------------
// Kernel 1b: W2 = W_hh @ W_hh   (W2[i][k] = sum_j W[i][j]*W[j][k])
// 512x512x512, 64x64 tiles, 256 threads, 4x4 microtile. ~10us.
// ---------------------------------------------------------------------------
__global__ __launch_bounds__(256)
void w2_kernel(const float* __restrict__ W)   // weight [512][1024], w_hh cols [0,512)
{
    __shared__ float As[32][68];   // [j][i]
    __shared__ float Bs[32][68];   // [j][k]

    const int tid = threadIdx.x;
    const int i0 = blockIdx.x * 64;
    const int k0g = blockIdx.y * 64;

    const int tx = tid & 15;
    const int ty = tid >> 4;

    float acc[4][4];
#pragma unroll
    for (int a = 0; a < 4; a++)
#pragma unroll
        for (int b = 0; b < 4; b++) acc[a][b] = 0.f;

#pragma unroll 1
    for (int jt = 0; jt < 16; jt++) {
        const int j0 = jt * 32;
        // A tile: 64 i-rows x 32 j  (transposed into As[j][i])
#pragma unroll
        for (int l = 0; l < 2; l++) {
            int idx = tid + l * 256;       // [0,512)
            int row = idx >> 3;            // i row 0..63
            int q   = idx & 7;
            float4 v = *reinterpret_cast<const float4*>(&W[(size_t)(i0 + row) * 1024 + j0 + q * 4]);
            As[q * 4 + 0][row] = v.x;
            As[q * 4 + 1][row] = v.y;
            As[q * 4 + 2][row] = v.z;
            As[q * 4 + 3][row] = v.w;
        }
        // B tile: 32 j-rows x 64 k
#pragma unroll
        for (int l = 0; l < 2; l++) {
            int idx = tid + l * 256;       // [0,512)
            int row = idx >> 4;            // j row 0..31
            int q   = idx & 15;
            float4 v = *reinterpret_cast<const float4*>(&W[(size_t)(j0 + row) * 1024 + k0g + q * 4]);
            Bs[row][q * 4 + 0] = v.x;
            Bs[row][q * 4 + 1] = v.y;
            Bs[row][q * 4 + 2] = v.z;
            Bs[row][q * 4 + 3] = v.w;
        }
        __syncthreads();

#pragma unroll
        for (int j = 0; j < 32; j++) {
            float a[4], b[4];
#pragma unroll
            for (int x = 0; x < 4; x++) a[x] = As[j][ty * 4 + x];
#pragma unroll
            for (int x = 0; x < 4; x++) b[x] = Bs[j][tx * 4 + x];
#pragma unroll
            for (int x = 0; x < 4; x++)
#pragma unroll
                for (int y = 0; y < 4; y++)
                    acc[x][y] = fmaf(a[x], b[y], acc[x][y]);
        }
        __syncthreads();
    }

#pragma unroll
    for (int x = 0; x < 4; x++)
#pragma unroll
        for (int y = 0; y < 4; y++)
            g_W2[(size_t)(i0 + ty * 4 + x) * 512 + k0g + tx * 4 + y] = acc[x][y];
}

// ---------------------------------------------------------------------------
// Kernel 2: recurrent-side parallel GEMM (pre/post phases). M = 16384 rows
// (r=0..1023, b=0..15), N=512, K=512, weights = w_hh.
//   phase 0 (pre):  C[r,b] = W @ xp_{2r}[b]  + xp_{2r+1}[b]
//                   A = out[2r slot], D=C = out[2r+1 slot]  (c_r for the scan)
//   phase 1 (post): C[r,b] = W @ h^{(2r)}[b] + xp_{2r}[b]
//                   A = (r==0 ? state : out[2r-1 slot]), D=C = out[2r slot]
// ---------------------------------------------------------------------------
__global__ __launch_bounds__(256)
void rec_gemm_kernel(const float* __restrict__ W,      // weight [512][1024]
                     const float* __restrict__ state,  // [16][512]
                     float* __restrict__ out,
                     int phase)
{
    __shared__ float As[32][132];
    __shared__ float Bs[32][68];

    const int tid = threadIdx.x;
    const int bm = blockIdx.x * 128;
    const int bn = blockIdx.y * 64;

    const int tx = tid & 15;
    const int ty = tid >> 4;

    float acc[8][4];
#pragma unroll
    for (int r = 0; r < 8; r++)
#pragma unroll
        for (int c = 0; c < 4; c++) acc[r][c] = 0.f;

#pragma unroll 1
    for (int kt = 0; kt < 16; kt++) {
        const int k0 = kt * 32;
        // A tile: 128 rows x 32 k, per-row base depends on phase
#pragma unroll
        for (int j = 0; j < 4; j++) {
            int idx = tid + j * 256;
            int row = idx >> 3;
            int q   = idx & 7;
            int m   = bm + row;
            int rr  = m >> 4;
            int bb  = m & 15;
            const float* arow;
            if (phase == 0) {
                arow = out + (size_t)(2 * rr) * BH + (size_t)bb * 512;
            } else {
                arow = (rr == 0) ? (state + (size_t)bb * 512)
                                 : (out + (size_t)(2 * rr - 1) * BH + (size_t)bb * 512);
            }
            float4 v = *reinterpret_cast<const float4*>(arow + k0 + q * 4);
            As[q * 4 + 0][row] = v.x;
            As[q * 4 + 1][row] = v.y;
            As[q * 4 + 2][row] = v.z;
            As[q * 4 + 3][row] = v.w;
        }
        // B tile: w_hh (cols [0,512) of weight)
#pragma unroll
        for (int j = 0; j < 2; j++) {
            int idx = tid + j * 256;
            int row = idx >> 3;
            int q   = idx & 7;
            float4 v = *reinterpret_cast<const float4*>(&W[(size_t)(bn + row) * 1024 + k0 + q * 4]);
            Bs[q * 4 + 0][row] = v.x;
            Bs[q * 4 + 1][row] = v.y;
            Bs[q * 4 + 2][row] = v.z;
            Bs[q * 4 + 3][row] = v.w;
        }
        __syncthreads();

#pragma unroll
        for (int k = 0; k < 32; k++) {
            float4 a0 = *reinterpret_cast<const float4*>(&As[k][ty * 8]);
            float4 a1 = *reinterpret_cast<const float4*>(&As[k][ty * 8 + 4]);
            float4 b  = *reinterpret_cast<const float4*>(&Bs[k][tx * 4]);
            float av[8] = {a0.x, a0.y, a0.z, a0.w, a1.x, a1.y, a1.z, a1.w};
            float bv[4] = {b.x, b.y, b.z, b.w};
#pragma unroll
            for (int r = 0; r < 8; r++)
#pragma unroll
                for (int c = 0; c < 4; c++)
                    acc[r][c] = fmaf(av[r], bv[c], acc[r][c]);
        }
        __syncthreads();
    }

    // epilogue: C = acc + D, in place (read D before write; same thread)
#pragma unroll
    for (int r = 0; r < 8; r++) {
        int m  = bm + ty * 8 + r;
        int rr = m >> 4;
        int bb = m & 15;
        size_t slot = (phase == 0) ? (size_t)(2 * rr + 1) : (size_t)(2 * rr);
        float* crow = out + slot * BH + (size_t)bb * 512 + bn + tx * 4;
#pragma unroll
        for (int c = 0; c < 4; c++) {
            float d = crow[c];
            crow[c] = acc[r][c] + d;
        }
    }
}

// ---------------------------------------------------------------------------
// Kernel 3: cluster scan — EXACT R5 protocol (proven 2958us), but iterating
// RR=1024 rounds with W2 (row stride 512) and c_r in the odd out slots:
//   h^{(2r+2)} = W2 @ h^{(2r)} + c_r ;  write out[2r+1] ; last at r=RR-1.
// ---------------------------------------------------------------------------
__global__ void __cluster_dims__(CLUSTER, 1, 1) __launch_bounds__(512, 1)
scan_kernel(const float* __restrict__ state,   // [16][512]
            float* __restrict__ out)           // [T][16][512] + last [16][512]
{
    __shared__ float hsh[2][512];              // double-buffered h
    __shared__ float red[8][65];               // k-split partials
    __shared__ __align__(8) u64 mbar[2];       // full[buf] barriers

    const int tid  = threadIdx.x;
    const int col  = tid & 63;
    const int ks   = tid >> 6;                 // k in [ks*64, ks*64+64)
    const int rank = blockIdx.x & (CLUSTER - 1);
    const int b    = blockIdx.x / CLUSTER;     // batch
    const int c0   = rank * 64;
    const int gcol = c0 + col;

    // ---- W2 slice into registers (f32x2-packed over k) ----
    u64 wreg[32];
    {
        const u64* wp = reinterpret_cast<const u64*>(
            g_W2 + (size_t)gcol * 512 + ks * 64);
#pragma unroll
        for (int j = 0; j < 32; j += 2) {
            ulonglong2 v = *reinterpret_cast<const ulonglong2*>(wp + j);
            wreg[j]     = v.x;
            wreg[j + 1] = v.y;
        }
    }

    // ---- init: h_0, barriers, cluster-wide visibility ----
    hsh[0][tid] = state[(size_t)b * 512 + tid];
    const uint32_t bar0 = smem_u32(&mbar[0]);
    const uint32_t bar1 = smem_u32(&mbar[1]);
    if (tid == 0) {
        asm volatile("mbarrier.init.shared.b64 [%0], 1;" :: "r"(bar0) : "memory");
        asm volatile("mbarrier.init.shared.b64 [%0], 1;" :: "r"(bar1) : "memory");
    }
    __syncthreads();
    asm volatile("barrier.cluster.arrive.aligned;" ::: "memory");
    asm volatile("barrier.cluster.wait.aligned;" ::: "memory");

    // ---- prefetch c_0 (odd slot 1) ----
    float xp = 0.f;
    if (tid < 64)
        xp = __ldcg(out + (size_t)1 * BH + (size_t)b * HH + c0 + tid);

    const uint32_t laddr_h0 = smem_u32(&hsh[0][gcol]);
    const uint32_t laddr_h1 = smem_u32(&hsh[1][gcol]);

#pragma unroll 1
    for (int t = 0; t < RR; t++) {
        const int rb = t & 1;
        const uint32_t barw = rb ? bar1 : bar0;

        // ---- 1. wait for h from all 8 CTAs (2048 tx bytes) ----
        if (t > 0) {
            if (tid == 0)
                asm volatile("mbarrier.arrive.expect_tx.shared.b64 _, [%0], 2048;"
                             :: "r"(barw) : "memory");
            const uint32_t parity = ((unsigned)(t - 1) >> 1) & 1u;
            uint32_t done;
            asm volatile(
                "{\n\t.reg .pred p;\n\t"
                "mbarrier.try_wait.parity.acquire.cta.shared::cta.b64 p, [%1], %2;\n\t"
                "selp.b32 %0, 1, 0, p;\n\t}"
                : "=r"(done) : "r"(barw), "r"(parity) : "memory");
            while (!done) {
                asm volatile(
                    "{\n\t.reg .pred p;\n\t"
                    "mbarrier.try_wait.parity.acquire.cta.shared::cta.b64 p, [%1], %2, 0x989680;\n\t"
                    "selp.b32 %0, 1, 0, p;\n\t}"
                    : "=r"(done) : "r"(barw), "r"(parity) : "memory");
            }
        }

        // ---- 2. compute: packed f32x2 dot over this thread's 64 k's ----
        u64 accp = 0ull;
        const u64* hp = reinterpret_cast<const u64*>(&hsh[rb][ks * 64]);
#pragma unroll
        for (int j = 0; j < 32; j += 2) {
            ulonglong2 h2 = *reinterpret_cast<const ulonglong2*>(hp + j);
            asm("fma.rn.f32x2 %0, %1, %2, %0;"
                : "+l"(accp) : "l"(wreg[j]),     "l"(h2.x));
            asm("fma.rn.f32x2 %0, %1, %2, %0;"
                : "+l"(accp) : "l"(wreg[j + 1]), "l"(h2.y));
        }
        {
            uint32_t lo, hi;
            asm("mov.b64 {%0, %1}, %2;" : "=r"(lo), "=r"(hi) : "l"(accp));
            red[ks][col] = __uint_as_float(lo) + __uint_as_float(hi);
        }
        __syncthreads();

        // ---- 3. finalize (tid<64): reduce, publish via st.async, store out ----
        if (tid < 64) {
            float s = 0.f;
#pragma unroll
            for (int r = 0; r < 8; r++) s += red[r][tid];
            const float hn = s + xp;

            if (t + 1 < RR) {
                // push h[gcol] to all 8 CTAs' hsh[rb^1] (gcol = c0+tid here)
                const uint32_t ldst = rb ? laddr_h0 : laddr_h1;
                const uint32_t lbar = rb ? bar0 : bar1;
#pragma unroll
                for (int r = 0; r < CLUSTER; r++) {
                    uint32_t raddr, rbar;
                    asm volatile("mapa.shared::cluster.u32 %0, %1, %2;"
                                 : "=r"(raddr) : "r"(ldst), "r"(r));
                    asm volatile("mapa.shared::cluster.u32 %0, %1, %2;"
                                 : "=r"(rbar) : "r"(lbar), "r"(r));
                    asm volatile(
                        "st.async.weak.shared::cluster.mbarrier::complete_tx::bytes.f32 [%0], %1, [%2];"
                        :: "r"(raddr), "f"(hn), "r"(rbar) : "memory");
                }
            }

            // out[2t+1] = h^{(2t+2)}
            const size_t off = (size_t)(2 * t + 1) * BH + (size_t)b * HH + c0 + tid;
            __stcg(out + off, hn);
            if (t == RR - 1)
                __stcg(out + (size_t)TT * BH + (size_t)b * HH + c0 + tid, hn);
            // prefetch c_{t+1} from out[2t+3]
            if (t + 1 < RR)
                xp = __ldcg(out + (size_t)(2 * t + 3) * BH + (size_t)b * HH + c0 + tid);
        }
    }

    // ---- drain ----
    asm volatile("barrier.cluster.arrive.aligned;" ::: "memory");
    asm volatile("barrier.cluster.wait.aligned;" ::: "memory");
}

// ---------------------------------------------------------------------------
// Launch: xproj -> W2 -> pre-GEMM (c_r into odd slots) -> scan (odd slots,
// 1024 rounds) -> post-GEMM (even slots).
// ---------------------------------------------------------------------------
extern "C" void kernel_launch(void* const* d_in, const int* in_sizes, int n_in,
                              void* d_out, int out_size) {
    const float* inputs = (const float*)d_in[0];  // [T][B][I]
    const float* state  = (const float*)d_in[1];  // [B][H]
    const float* weight = (const float*)d_in[2];  // [H][I+H]
    const float* bias   = (const float*)d_in[3];  // [H]
    float* out = (float*)d_out;                   // [T][B][H] outputs, then [B][H] last

    dim3 g1(256, 8);   // M=32768 / 128, N=512 / 64
    xproj_kernel<<<g1, 256>>>(inputs, weight, bias, out);

    dim3 gw(8, 8);     // 512/64 x 512/64
    w2_kernel<<<gw, 256>>>(weight);

    dim3 g2(128, 8);   // M=16384 / 128, N=512 / 64
    rec_gemm_kernel<<<g2, 256>>>(weight, state, out, 0);   // pre: c_r -> odd slots

    scan_kernel<<<BB * CLUSTER, 512>>>(state, out);        // odd slots

    rec_gemm_kernel<<<g2, 256>>>(weight, state, out, 1);   // post: even slots

    (void)in_sizes; (void)n_in; (void)out_size;
}

// round 11
// speedup vs baseline: 2.6057x; 1.1835x over previous
#include <cuda_runtime.h>
#include <cuda_bf16.h>
#include <cstdint>

typedef unsigned long long u64;

// Problem dims
#define TT 2048
#define BB 16
#define II 512
#define HH 512
#define BH (BB*HH)   // 8192
#define RR (TT/4)    // 512 scan rounds (4-step blocking)

#define CLUSTER 8    // CTAs per cluster = 1 batch per cluster, 64 cols per CTA

// Scratch: W^2 and W^4, row-major [512][512]. Static __device__ (legal).
__device__ float g_W2[HH * HH];
__device__ float g_W4[HH * HH];

static __device__ __forceinline__ uint32_t smem_u32(const void* p) {
    uint32_t a;
    asm("{ .reg .u64 t; cvta.to.shared.u64 t, %1; cvt.u32.u64 %0, t; }"
        : "=r"(a) : "l"(p));
    return a;
}

#define FMA2(acc, a, b) \
    asm("fma.rn.f32x2 %0, %1, %2, %0;" : "+l"(acc) : "l"(a), "l"(b))
#define SPLAT2(dst, f) \
    asm("mov.b64 %0, {%1, %1};" : "=l"(dst) : "r"(__float_as_uint(f)))

// ---------------------------------------------------------------------------
// Kernel 1: x_proj[t,b,h] = sum_i inputs[t,b,i] * w_xh[h][i] + bias[h]
// 128x64 tile, 256 threads. Inner loop in packed f32x2 (m-pairs).
// ---------------------------------------------------------------------------
__global__ __launch_bounds__(256)
void xproj_kernel(const float* __restrict__ A,      // inputs [M][512]
                  const float* __restrict__ W,      // weight [512][1024]
                  const float* __restrict__ bias,   // [512]
                  float* __restrict__ out)          // [M][512]
{
    __shared__ float As[32][132];
    __shared__ float Bs[32][68];

    const int tid = threadIdx.x;
    const int bm = blockIdx.x * 128;
    const int bn = blockIdx.y * 64;

    const int tx = tid & 15;
    const int ty = tid >> 4;

    u64 acc2[4][4];   // [m-pair][col], packed (row 2mp, row 2mp+1)
#pragma unroll
    for (int r = 0; r < 4; r++)
#pragma unroll
        for (int c = 0; c < 4; c++) acc2[r][c] = 0ull;

#pragma unroll 1
    for (int kt = 0; kt < 16; kt++) {
        const int k0 = kt * 32;
#pragma unroll
        for (int j = 0; j < 4; j++) {
            int idx = tid + j * 256;
            int row = idx >> 3;
            int q   = idx & 7;
            float4 v = *reinterpret_cast<const float4*>(&A[(size_t)(bm + row) * 512 + k0 + q * 4]);
            As[q * 4 + 0][row] = v.x;
            As[q * 4 + 1][row] = v.y;
            As[q * 4 + 2][row] = v.z;
            As[q * 4 + 3][row] = v.w;
        }
#pragma unroll
        for (int j = 0; j < 2; j++) {
            int idx = tid + j * 256;
            int row = idx >> 3;
            int q   = idx & 7;
            float4 v = *reinterpret_cast<const float4*>(&W[(size_t)(bn + row) * 1024 + 512 + k0 + q * 4]);
            Bs[q * 4 + 0][row] = v.x;
            Bs[q * 4 + 1][row] = v.y;
            Bs[q * 4 + 2][row] = v.z;
            Bs[q * 4 + 3][row] = v.w;
        }
        __syncthreads();

#pragma unroll
        for (int k = 0; k < 32; k++) {
            const ulonglong2* ap = reinterpret_cast<const ulonglong2*>(&As[k][ty * 8]);
            ulonglong2 a01 = ap[0];
            ulonglong2 a23 = ap[1];
            float4 b = *reinterpret_cast<const float4*>(&Bs[k][tx * 4]);
            u64 bs[4];
            SPLAT2(bs[0], b.x); SPLAT2(bs[1], b.y);
            SPLAT2(bs[2], b.z); SPLAT2(bs[3], b.w);
            u64 apair[4] = {a01.x, a01.y, a23.x, a23.y};
#pragma unroll
            for (int r = 0; r < 4; r++)
#pragma unroll
                for (int c = 0; c < 4; c++)
                    FMA2(acc2[r][c], apair[r], bs[c]);
        }
        __syncthreads();
    }

#pragma unroll
    for (int r = 0; r < 4; r++) {
        size_t row0 = (size_t)(bm + ty * 8 + 2 * r) * 512 + bn + tx * 4;
#pragma unroll
        for (int c = 0; c < 4; c++) {
            uint32_t lo, hi;
            asm("mov.b64 {%0, %1}, %2;" : "=r"(lo), "=r"(hi) : "l"(acc2[r][c]));
            float bv = bias[bn + tx * 4 + c];
            out[row0 + c]       = __uint_as_float(lo) + bv;
            out[row0 + 512 + c] = __uint_as_float(hi) + bv;
        }
    }
}

// ---------------------------------------------------------------------------
// Kernel 1b: matrix squaring. which=0: g_W2 = Whh @ Whh (src stride 1024)
//            which=1: g_W4 = g_W2 @ g_W2 (stride 512). ~10us each.
// ---------------------------------------------------------------------------
__global__ __launch_bounds__(256)
void mat_sq_kernel(const float* __restrict__ W, int which)
{
    __shared__ float As[32][68];   // [j][i]
    __shared__ float Bs[32][68];   // [j][k]

    const int tid = threadIdx.x;
    const int i0 = blockIdx.x * 64;
    const int k0g = blockIdx.y * 64;

    const int tx = tid & 15;
    const int ty = tid >> 4;

    float acc[4][4];
#pragma unroll
    for (int a = 0; a < 4; a++)
#pragma unroll
        for (int b = 0; b < 4; b++) acc[a][b] = 0.f;

#pragma unroll 1
    for (int jt = 0; jt < 16; jt++) {
        const int j0 = jt * 32;
#pragma unroll
        for (int l = 0; l < 2; l++) {
            int idx = tid + l * 256;
            int row = idx >> 3;
            int q   = idx & 7;
            const float* src = which
                ? (g_W2 + (size_t)(i0 + row) * 512 + j0 + q * 4)
                : (W    + (size_t)(i0 + row) * 1024 + j0 + q * 4);
            float4 v = *reinterpret_cast<const float4*>(src);
            As[q * 4 + 0][row] = v.x;
            As[q * 4 + 1][row] = v.y;
            As[q * 4 + 2][row] = v.z;
            As[q * 4 + 3][row] = v.w;
        }
#pragma unroll
        for (int l = 0; l < 2; l++) {
            int idx = tid + l * 256;
            int row = idx >> 4;
            int q   = idx & 15;
            const float* src = which
                ? (g_W2 + (size_t)(j0 + row) * 512 + k0g + q * 4)
                : (W    + (size_t)(j0 + row) * 1024 + k0g + q * 4);
            float4 v = *reinterpret_cast<const float4*>(src);
            Bs[row][q * 4 + 0] = v.x;
            Bs[row][q * 4 + 1] = v.y;
            Bs[row][q * 4 + 2] = v.z;
            Bs[row][q * 4 + 3] = v.w;
        }
        __syncthreads();

#pragma unroll
        for (int j = 0; j < 32; j++) {
            float a[4], b[4];
#pragma unroll
            for (int x = 0; x < 4; x++) a[x] = As[j][ty * 4 + x];
#pragma unroll
            for (int x = 0; x < 4; x++) b[x] = Bs[j][tx * 4 + x];
#pragma unroll
            for (int x = 0; x < 4; x++)
#pragma unroll
                for (int y = 0; y < 4; y++)
                    acc[x][y] = fmaf(a[x], b[y], acc[x][y]);
        }
        __syncthreads();
    }

    float* dst = which ? g_W4 : g_W2;
#pragma unroll
    for (int x = 0; x < 4; x++)
#pragma unroll
        for (int y = 0; y < 4; y++)
            dst[(size_t)(i0 + ty * 4 + x) * 512 + k0g + tx * 4 + y] = acc[x][y];
}

// ---------------------------------------------------------------------------
// Kernel 2: recurrent-side parallel GEMMs. Row m -> (rr = m>>4, bb = m&15).
//  phase 0 (pre1,  W,  M=16384): c1_rr = W @ out[2rr] + out[2rr+1] -> out[2rr+1]
//  phase 2 (pre2,  W2, M=8192):  c2_rr = W2 @ out[4rr+1] + out[4rr+3] -> out[4rr+3]
//  phase 3 (post1, W2, M=8192):  h_{4rr+1} = W2 @ (rr? out[4rr-1] : state) + out[4rr+1] -> out[4rr+1]
//  phase 1 (post2, W,  M=16384): h_{2rr} = W @ (rr? out[2rr-1] : state) + out[2rr] -> out[2rr]
//  wsel: 0 = weight (stride 1024, w_hh cols), 1 = g_W2 (stride 512)
// ---------------------------------------------------------------------------
__global__ __launch_bounds__(256)
void rec_gemm_kernel(const float* __restrict__ W,      // weight [512][1024]
                     const float* __restrict__ state,  // [16][512]
                     float* __restrict__ out,
                     int phase, int wsel)
{
    __shared__ float As[32][132];
    __shared__ float Bs[32][68];

    const int tid = threadIdx.x;
    const int bm = blockIdx.x * 128;
    const int bn = blockIdx.y * 64;

    const int tx = tid & 15;
    const int ty = tid >> 4;

    u64 acc2[4][4];
#pragma unroll
    for (int r = 0; r < 4; r++)
#pragma unroll
        for (int c = 0; c < 4; c++) acc2[r][c] = 0ull;

#pragma unroll 1
    for (int kt = 0; kt < 16; kt++) {
        const int k0 = kt * 32;
#pragma unroll
        for (int j = 0; j < 4; j++) {
            int idx = tid + j * 256;
            int row = idx >> 3;
            int q   = idx & 7;
            int m   = bm + row;
            int rr  = m >> 4;
            int bb  = m & 15;
            const float* arow;
            if (phase == 0) {
                arow = out + (size_t)(2 * rr) * BH + (size_t)bb * 512;
            } else if (phase == 1) {
                arow = (rr == 0) ? (state + (size_t)bb * 512)
                                 : (out + (size_t)(2 * rr - 1) * BH + (size_t)bb * 512);
            } else if (phase == 2) {
                arow = out + (size_t)(4 * rr + 1) * BH + (size_t)bb * 512;
            } else { // phase 3
                arow = (rr == 0) ? (state + (size_t)bb * 512)
                                 : (out + (size_t)(4 * rr - 1) * BH + (size_t)bb * 512);
            }
            float4 v = *reinterpret_cast<const float4*>(arow + k0 + q * 4);
            As[q * 4 + 0][row] = v.x;
            As[q * 4 + 1][row] = v.y;
            As[q * 4 + 2][row] = v.z;
            As[q * 4 + 3][row] = v.w;
        }
#pragma unroll
        for (int j = 0; j < 2; j++) {
            int idx = tid + j * 256;
            int row = idx >> 3;
            int q   = idx & 7;
            const float* src = wsel
                ? (g_W2 + (size_t)(bn + row) * 512 + k0 + q * 4)
                : (W    + (size_t)(bn + row) * 1024 + k0 + q * 4);
            float4 v = *reinterpret_cast<const float4*>(src);
            Bs[q * 4 + 0][row] = v.x;
            Bs[q * 4 + 1][row] = v.y;
            Bs[q * 4 + 2][row] = v.z;
            Bs[q * 4 + 3][row] = v.w;
        }
        __syncthreads();

#pragma unroll
        for (int k = 0; k < 32; k++) {
            const ulonglong2* ap = reinterpret_cast<const ulonglong2*>(&As[k][ty * 8]);
            ulonglong2 a01 = ap[0];
            ulonglong2 a23 = ap[1];
            float4 b = *reinterpret_cast<const float4*>(&Bs[k][tx * 4]);
            u64 bs[4];
            SPLAT2(bs[0], b.x); SPLAT2(bs[1], b.y);
            SPLAT2(bs[2], b.z); SPLAT2(bs[3], b.w);
            u64 apair[4] = {a01.x, a01.y, a23.x, a23.y};
#pragma unroll
            for (int r = 0; r < 4; r++)
#pragma unroll
                for (int c = 0; c < 4; c++)
                    FMA2(acc2[r][c], apair[r], bs[c]);
        }
        __syncthreads();
    }

    // epilogue: C = acc + D, in place
#pragma unroll
    for (int r = 0; r < 4; r++) {
#pragma unroll
        for (int par = 0; par < 2; par++) {
            int m  = bm + ty * 8 + 2 * r + par;
            int rr = m >> 4;
            int bb = m & 15;
            size_t slot;
            if (phase == 0)      slot = (size_t)(2 * rr + 1);
            else if (phase == 1) slot = (size_t)(2 * rr);
            else if (phase == 2) slot = (size_t)(4 * rr + 3);
            else                 slot = (size_t)(4 * rr + 1);
            float* crow = out + slot * BH + (size_t)bb * 512 + bn + tx * 4;
#pragma unroll
            for (int c = 0; c < 4; c++) {
                uint32_t lo, hi;
                asm("mov.b64 {%0, %1}, %2;" : "=r"(lo), "=r"(hi) : "l"(acc2[r][c]));
                float v = par ? __uint_as_float(hi) : __uint_as_float(lo);
                float d = crow[c];
                crow[c] = v + d;
            }
        }
    }
}

// ---------------------------------------------------------------------------
// Kernel 3: cluster scan — proven R5 protocol, 512 rounds with W4:
//   h_{4q+3} = W4 @ h_{4q-1} + c2_q ; c2_q lives in out[4q+3] (overwritten).
// ---------------------------------------------------------------------------
__global__ void __cluster_dims__(CLUSTER, 1, 1) __launch_bounds__(512, 1)
scan_kernel(const float* __restrict__ state,   // [16][512]
            float* __restrict__ out)           // [T][16][512] + last [16][512]
{
    __shared__ float hsh[2][512];              // double-buffered h
    __shared__ float red[8][65];               // k-split partials
    __shared__ __align__(8) u64 mbar[2];       // full[buf] barriers

    const int tid  = threadIdx.x;
    const int col  = tid & 63;
    const int ks   = tid >> 6;                 // k in [ks*64, ks*64+64)
    const int rank = blockIdx.x & (CLUSTER - 1);
    const int b    = blockIdx.x / CLUSTER;     // batch
    const int c0   = rank * 64;
    const int gcol = c0 + col;

    // ---- W4 slice into registers (f32x2-packed over k) ----
    u64 wreg[32];
    {
        const u64* wp = reinterpret_cast<const u64*>(
            g_W4 + (size_t)gcol * 512 + ks * 64);
#pragma unroll
        for (int j = 0; j < 32; j += 2) {
            ulonglong2 v = *reinterpret_cast<const ulonglong2*>(wp + j);
            wreg[j]     = v.x;
            wreg[j + 1] = v.y;
        }
    }

    // ---- init: h_{-1} = state, barriers, cluster-wide visibility ----
    hsh[0][tid] = state[(size_t)b * 512 + tid];
    const uint32_t bar0 = smem_u32(&mbar[0]);
    const uint32_t bar1 = smem_u32(&mbar[1]);
    if (tid == 0) {
        asm volatile("mbarrier.init.shared.b64 [%0], 1;" :: "r"(bar0) : "memory");
        asm volatile("mbarrier.init.shared.b64 [%0], 1;" :: "r"(bar1) : "memory");
    }
    __syncthreads();
    asm volatile("barrier.cluster.arrive.aligned;" ::: "memory");
    asm volatile("barrier.cluster.wait.aligned;" ::: "memory");

    // ---- prefetch c2_0 (slot 3) ----
    float xp = 0.f;
    if (tid < 64)
        xp = __ldcg(out + (size_t)3 * BH + (size_t)b * HH + c0 + tid);

    const uint32_t laddr_h0 = smem_u32(&hsh[0][gcol]);
    const uint32_t laddr_h1 = smem_u32(&hsh[1][gcol]);

#pragma unroll 1
    for (int t = 0; t < RR; t++) {
        const int rb = t & 1;
        const uint32_t barw = rb ? bar1 : bar0;

        // ---- 1. wait for h from all 8 CTAs (2048 tx bytes) ----
        if (t > 0) {
            if (tid == 0)
                asm volatile("mbarrier.arrive.expect_tx.shared.b64 _, [%0], 2048;"
                             :: "r"(barw) : "memory");
            const uint32_t parity = ((unsigned)(t - 1) >> 1) & 1u;
            uint32_t done;
            asm volatile(
                "{\n\t.reg .pred p;\n\t"
                "mbarrier.try_wait.parity.acquire.cta.shared::cta.b64 p, [%1], %2;\n\t"
                "selp.b32 %0, 1, 0, p;\n\t}"
                : "=r"(done) : "r"(barw), "r"(parity) : "memory");
            while (!done) {
                asm volatile(
                    "{\n\t.reg .pred p;\n\t"
                    "mbarrier.try_wait.parity.acquire.cta.shared::cta.b64 p, [%1], %2, 0x989680;\n\t"
                    "selp.b32 %0, 1, 0, p;\n\t}"
                    : "=r"(done) : "r"(barw), "r"(parity) : "memory");
            }
        }

        // ---- 2. compute: packed f32x2 dot over this thread's 64 k's ----
        u64 accp = 0ull;
        const u64* hp = reinterpret_cast<const u64*>(&hsh[rb][ks * 64]);
#pragma unroll
        for (int j = 0; j < 32; j += 2) {
            ulonglong2 h2 = *reinterpret_cast<const ulonglong2*>(hp + j);
            FMA2(accp, wreg[j],     h2.x);
            FMA2(accp, wreg[j + 1], h2.y);
        }
        {
            uint32_t lo, hi;
            asm("mov.b64 {%0, %1}, %2;" : "=r"(lo), "=r"(hi) : "l"(accp));
            red[ks][col] = __uint_as_float(lo) + __uint_as_float(hi);
        }
        __syncthreads();

        // ---- 3. finalize (tid<64): reduce, publish via st.async, store out ----
        if (tid < 64) {
            float s = 0.f;
#pragma unroll
            for (int r = 0; r < 8; r++) s += red[r][tid];
            const float hn = s + xp;

            if (t + 1 < RR) {
                const uint32_t ldst = rb ? laddr_h0 : laddr_h1;
                const uint32_t lbar = rb ? bar0 : bar1;
#pragma unroll
                for (int r = 0; r < CLUSTER; r++) {
                    uint32_t raddr, rbar;
                    asm volatile("mapa.shared::cluster.u32 %0, %1, %2;"
                                 : "=r"(raddr) : "r"(ldst), "r"(r));
                    asm volatile("mapa.shared::cluster.u32 %0, %1, %2;"
                                 : "=r"(rbar) : "r"(lbar), "r"(r));
                    asm volatile(
                        "st.async.weak.shared::cluster.mbarrier::complete_tx::bytes.f32 [%0], %1, [%2];"
                        :: "r"(raddr), "f"(hn), "r"(rbar) : "memory");
                }
            }

            // out[4t+3] = h_{4t+3}
            const size_t off = (size_t)(4 * t + 3) * BH + (size_t)b * HH + c0 + tid;
            __stcg(out + off, hn);
            if (t == RR - 1)
                __stcg(out + (size_t)TT * BH + (size_t)b * HH + c0 + tid, hn);
            // prefetch c2_{t+1} from out[4t+7]
            if (t + 1 < RR)
                xp = __ldcg(out + (size_t)(4 * t + 7) * BH + (size_t)b * HH + c0 + tid);
        }
    }

    // ---- drain ----
    asm volatile("barrier.cluster.arrive.aligned;" ::: "memory");
    asm volatile("barrier.cluster.wait.aligned;" ::: "memory");
}

// ---------------------------------------------------------------------------
// Launch: xproj -> W2 -> W4 -> pre1 -> pre2 -> scan (512 rounds) ->
//         post1 -> post2.
// ---------------------------------------------------------------------------
extern "C" void kernel_launch(void* const* d_in, const int* in_sizes, int n_in,
                              void* d_out, int out_size) {
    const float* inputs = (const float*)d_in[0];  // [T][B][I]
    const float* state  = (const float*)d_in[1];  // [B][H]
    const float* weight = (const float*)d_in[2];  // [H][I+H]
    const float* bias   = (const float*)d_in[3];  // [H]
    float* out = (float*)d_out;                   // [T][B][H] outputs, then [B][H] last

    dim3 g1(256, 8);   // M=32768 / 128, N=512 / 64
    xproj_kernel<<<g1, 256>>>(inputs, weight, bias, out);

    dim3 gw(8, 8);     // 512/64 x 512/64
    mat_sq_kernel<<<gw, 256>>>(weight, 0);   // g_W2 = Whh^2
    mat_sq_kernel<<<gw, 256>>>(weight, 1);   // g_W4 = g_W2^2

    dim3 g16k(128, 8); // M=16384 / 128
    dim3 g8k(64, 8);   // M=8192 / 128

    rec_gemm_kernel<<<g16k, 256>>>(weight, state, out, 0, 0);  // pre1:  c1 -> odd slots
    rec_gemm_kernel<<<g8k,  256>>>(weight, state, out, 2, 1);  // pre2:  c2 -> slots 4q+3

    scan_kernel<<<BB * CLUSTER, 512>>>(state, out);            // 512 rounds, W4

    rec_gemm_kernel<<<g8k,  256>>>(weight, state, out, 3, 1);  // post1: slots 4q+1
    rec_gemm_kernel<<<g16k, 256>>>(weight, state, out, 1, 0);  // post2: even slots

    (void)in_sizes; (void)n_in; (void)out_size;
}